// round 16
// baseline (speedup 1.0000x reference)
#include <cuda_runtime.h>
#include <cuda_fp16.h>
#include <math.h>
#include <stdint.h>

#define Bb 8
#define Tt 8192
#define Dd 512
#define Mm 512
#define PD 32
#define LC 16
#define NC (Tt / LC)      // 512

// ---- scratch (device globals; no allocation allowed) ----
__device__ float g_chunkSum[Bb * NC * Dd];            // 8 MB
__device__ float g_chunkPre[Bb * NC * Dd];            // 8 MB
__device__ float g_fine[Bb * NC * 3 * Dd];            // 24 MB: cumulative 4/8/12-row partials
__device__ float g_ffb[Mm * Dd];                      // ff @ W2 + bias (fp32, batch-independent)
__device__ int   g_s[Bb * Mm];
__device__ int   g_e[Bb * Mm];
__device__ __half g_Xh[Bb * Mm * Dd];                 // fp16(X)
__device__ __half g_WhT[Dd * Dd];                     // W1^T [n][k], fp16 hi
__device__ __half g_WlT[Dd * Dd];                     // W1^T [n][k], fp16 lo (W - Wh)

// ================ kFused: 1D grid of 128-thread blocks ================
#define NBLK_CHUNK (NC * Bb)                 // 4096
#define NBLK_BND   32
#define NBLK_FFB   (Mm * 4)                  // 2048
#define NBLK_W     (Dd * 4)                  // 2048
#define NBLK_TOTAL (NBLK_CHUNK + NBLK_BND + NBLK_FFB + NBLK_W)

__global__ void __launch_bounds__(128) kFused(const float* __restrict__ frame,
                                              const void* __restrict__ bounds,
                                              const float* __restrict__ W,
                                              const float* __restrict__ bias) {
    int bid = blockIdx.x, tid = threadIdx.x;

    if (bid < NBLK_CHUNK) {
        int c = bid & (NC - 1), b = bid >> 9, t4 = tid;
        const float4* f = (const float4*)frame;
        float4* fine = (float4*)g_fine;
        float4 acc = make_float4(0.f, 0.f, 0.f, 0.f);
        int base = (b * Tt + c * LC) * (Dd / 4) + t4;
        size_t fbase = ((size_t)(b * NC + c) * 3) * (Dd / 4) + t4;
        #pragma unroll
        for (int r = 0; r < LC; r++) {
            float4 v = f[base + r * (Dd / 4)];
            acc.x += v.x; acc.y += v.y; acc.z += v.z; acc.w += v.w;
            if (r == 3)  fine[fbase + 0 * (Dd / 4)] = acc;
            if (r == 7)  fine[fbase + 1 * (Dd / 4)] = acc;
            if (r == 11) fine[fbase + 2 * (Dd / 4)] = acc;
        }
        ((float4*)g_chunkSum)[(b * NC + c) * (Dd / 4) + t4] = acc;
        return;
    }
    bid -= NBLK_CHUNK;

    if (bid < NBLK_BND) {
        __shared__ int flag;
        if (tid == 0) flag = 0;
        __syncthreads();
        {
            const int* w = (const int*)bounds;
            if (w[2 * tid + 1] != 0) flag = 1;   // benign race
        }
        __syncthreads();
        bool isI64 = (flag == 0);
        int idx = bid * 128 + tid;               // 0..4095
        int b = idx >> 9, m = idx & 511;
        long long sv, ev;
        if (isI64) {
            const long long* p = (const long long*)bounds;
            sv = p[((long long)b * Mm + m) * 2];
            ev = p[((long long)b * Mm + m) * 2 + 1];
        } else {
            const int* p = (const int*)bounds;
            sv = p[(b * Mm + m) * 2];
            ev = p[(b * Mm + m) * 2 + 1];
        }
        long long s = sv; if (s < 0) s = 0; if (s > Tt - 1) s = Tt - 1;
        long long e = ev; if (e > Tt) e = Tt; if (e < s + 1) e = s + 1;
        g_s[b * Mm + m] = (int)s;
        g_e[b * Mm + m] = (int)e;
        return;
    }
    bid -= NBLK_BND;

    if (bid < NBLK_FFB) {
        int m = bid >> 2, q = bid & 3;
        int n = q * 128 + tid;
        __shared__ float ffs[PD];
        if (tid < PD / 2) {
            double pos = (double)m / (double)(Mm - 1);
            double f = exp(log(1000.0) * (double)tid / (double)(PD / 2 - 1));
            double a = pos * f;
            ffs[tid] = (float)sin(a);
            ffs[PD / 2 + tid] = (float)cos(a);
        }
        __syncthreads();
        float acc = bias[n];
        #pragma unroll
        for (int j = 0; j < PD; j++)
            acc = fmaf(ffs[j], W[(Dd + j) * Dd + n], acc);
        g_ffb[m * Dd + n] = acc;
        return;
    }
    bid -= NBLK_FFB;

    {
        int k = bid >> 2, q = bid & 3;
        int n = q * 128 + tid;
        float v = W[k * Dd + n];
        __half h = __float2half_rn(v);
        g_WhT[n * Dd + k] = h;
        g_WlT[n * Dd + k] = __float2half_rn(v - __half2float(h));
    }
}

// ---------------- kScan: exclusive prefix over NC chunks (4 warps/block) ----------------
__global__ void __launch_bounds__(128) kScan() {
    int d4 = blockIdx.x, b = blockIdx.y;
    int tid = threadIdx.x, wid = tid >> 5, lane = tid & 31;
    __shared__ float4 wtot[4];

    const float4* cs = (const float4*)g_chunkSum;
    float4* cp = (float4*)g_chunkPre;
    const int CPL = 4;
    int cbase = (wid * 32 + lane) * CPL;

    float4 v[CPL];
    float4 s = make_float4(0.f, 0.f, 0.f, 0.f);
    #pragma unroll
    for (int j = 0; j < CPL; j++) {
        v[j] = cs[(b * NC + cbase + j) * (Dd / 4) + d4];
        s.x += v[j].x; s.y += v[j].y; s.z += v[j].z; s.w += v[j].w;
    }
    float4 incl = s;
    #pragma unroll
    for (int off = 1; off < 32; off <<= 1) {
        float nx = __shfl_up_sync(0xffffffffu, incl.x, off);
        float ny = __shfl_up_sync(0xffffffffu, incl.y, off);
        float nz = __shfl_up_sync(0xffffffffu, incl.z, off);
        float nw = __shfl_up_sync(0xffffffffu, incl.w, off);
        if (lane >= off) { incl.x += nx; incl.y += ny; incl.z += nz; incl.w += nw; }
    }
    if (lane == 31) wtot[wid] = incl;
    __syncthreads();
    float4 wpre = make_float4(0.f, 0.f, 0.f, 0.f);
    #pragma unroll
    for (int w = 0; w < 4; w++) {
        if (w < wid) {
            float4 t = wtot[w];
            wpre.x += t.x; wpre.y += t.y; wpre.z += t.z; wpre.w += t.w;
        }
    }
    float4 run = make_float4(wpre.x + incl.x - s.x, wpre.y + incl.y - s.y,
                             wpre.z + incl.z - s.z, wpre.w + incl.w - s.w);
    #pragma unroll
    for (int j = 0; j < CPL; j++) {
        cp[(b * NC + cbase + j) * (Dd / 4) + d4] = run;
        run.x += v[j].x; run.y += v[j].y; run.z += v[j].z; run.w += v[j].w;
    }
}

// ---------------- kGather: segment means -> fp16 (2-level prefix) ----------------
__global__ void __launch_bounds__(128) kGather(const float* __restrict__ frame) {
    int m = blockIdx.x, b = blockIdx.y, t4 = threadIdx.x;
    int idx = b * Mm + m;
    int s = g_s[idx], e = g_e[idx];
    int csk = s >> 4;
    int cek = e >> 4; if (cek > NC - 1) cek = NC - 1;

    const float4* f  = (const float4*)frame;
    const float4* cp = (const float4*)g_chunkPre;
    const float4* fine = (const float4*)g_fine;

    float4 accs = cp[(b * NC + csk) * (Dd / 4) + t4];
    int fs = (s - csk * LC) >> 2;
    if (fs > 0) {
        float4 fv = fine[((size_t)(b * NC + csk) * 3 + (fs - 1)) * (Dd / 4) + t4];
        accs.x += fv.x; accs.y += fv.y; accs.z += fv.z; accs.w += fv.w;
    }
    for (int t = csk * LC + 4 * fs; t < s; t++) {
        float4 v = f[(b * Tt + t) * (Dd / 4) + t4];
        accs.x += v.x; accs.y += v.y; accs.z += v.z; accs.w += v.w;
    }
    float4 acce = cp[(b * NC + cek) * (Dd / 4) + t4];
    int de = e - cek * LC;
    int fe = de >> 2; if (fe > 3) fe = 3;
    if (fe > 0) {
        float4 fv = fine[((size_t)(b * NC + cek) * 3 + (fe - 1)) * (Dd / 4) + t4];
        acce.x += fv.x; acce.y += fv.y; acce.z += fv.z; acce.w += fv.w;
    }
    for (int t = cek * LC + 4 * fe; t < e; t++) {
        float4 v = f[(b * Tt + t) * (Dd / 4) + t4];
        acce.x += v.x; acce.y += v.y; acce.z += v.z; acce.w += v.w;
    }

    float inv = 1.f / (float)(e - s);
    __half2 p0 = __floats2half2_rn((acce.x - accs.x) * inv, (acce.y - accs.y) * inv);
    __half2 p1 = __floats2half2_rn((acce.z - accs.z) * inv, (acce.w - accs.w) * inv);
    uint2 hh;
    hh.x = *(uint32_t*)&p0;
    hh.y = *(uint32_t*)&p1;
    *(uint2*)(g_Xh + (size_t)idx * Dd + 4 * t4) = hh;
}

// ================= mma.sync fp16 2-term GEMM, K=512, cp.async 4-stage =================
// out[4096,512] = Xh @ (Wh + Wl) + ffb.
// CTA tile 64(m) x 128(n), KT=32. 8 warps = 2(m) x 4(n); warp tile 32x32.
// smem/CTA = 102.4 KB -> 2 CTAs per SM; grid = 256 CTAs (single wave at occ 2).

#define KT 32
#define SROW 40                              // padded row stride (fp16 elems); 80 B
#define A_ROWS 64
#define B_ROWS 128
#define A_TILE_B (A_ROWS * SROW * 2)         // 5120 B
#define B_TILE_B (B_ROWS * SROW * 2)         // 10240 B
#define STAGE_B (A_TILE_B + 2 * B_TILE_B)    // 25600 B
#define NSTAGES 4
#define SM_BYTES (NSTAGES * STAGE_B)         // 102400 B

static __device__ __forceinline__ uint32_t smem_u32(const void* p) {
    uint32_t a;
    asm("{ .reg .u64 t; cvta.to.shared.u64 t, %1; cvt.u32.u64 %0, t; }" : "=r"(a) : "l"(p));
    return a;
}
static __device__ __forceinline__ void cpasync16(uint32_t saddr, const void* gptr) {
    asm volatile("cp.async.cg.shared.global [%0], [%1], 16;" :: "r"(saddr), "l"(gptr));
}
static __device__ __forceinline__ void cpcommit() {
    asm volatile("cp.async.commit_group;" ::: "memory");
}
template <int N>
static __device__ __forceinline__ void cpwait() {
    asm volatile("cp.async.wait_group %0;" :: "n"(N) : "memory");
}
static __device__ __forceinline__ void ldsm4(uint32_t addr, uint32_t* r) {
    asm volatile("ldmatrix.sync.aligned.m8n8.x4.shared.b16 {%0,%1,%2,%3}, [%4];"
                 : "=r"(r[0]), "=r"(r[1]), "=r"(r[2]), "=r"(r[3]) : "r"(addr));
}
static __device__ __forceinline__ void mma16816(float* c, const uint32_t* a, uint32_t b0, uint32_t b1) {
    asm volatile(
        "mma.sync.aligned.m16n8k16.row.col.f32.f16.f16.f32 "
        "{%0,%1,%2,%3},{%4,%5,%6,%7},{%8,%9},{%0,%1,%2,%3};"
        : "+f"(c[0]), "+f"(c[1]), "+f"(c[2]), "+f"(c[3])
        : "r"(a[0]), "r"(a[1]), "r"(a[2]), "r"(a[3]), "r"(b0), "r"(b1));
}

__global__ void __launch_bounds__(256, 2)
kGemmMMA(float* __restrict__ out) {
    extern __shared__ __align__(16) char sm[];
    uint32_t sb = smem_u32(sm);
    int tid = threadIdx.x;
    int wid = tid >> 5, lane = tid & 31;
    int n0 = blockIdx.x * 128, m0 = blockIdx.y * A_ROWS;
    int wr = wid >> 2, wc = wid & 3;     // warp tile at (wr*32 m, wc*32 n)

    const __half* gA  = g_Xh  + (size_t)m0 * Dd;
    const __half* gBh = g_WhT + (size_t)n0 * Dd;
    const __half* gBl = g_WlT + (size_t)n0 * Dd;

    // loader: A = 256 16B-chunks (1/thread); Bh,Bl = 512 chunks each (2/thread each)
    const int arow = tid >> 2, acq = tid & 3;

    auto load_stage = [&](int st, int k0) {
        uint32_t sbase = sb + st * STAGE_B;
        // A
        {
            uint32_t soff = arow * (SROW * 2) + acq * 16;
            cpasync16(sbase + soff, gA + (size_t)arow * Dd + k0 + acq * 8);
        }
        // Bh, Bl
        #pragma unroll
        for (int i = 0; i < 2; i++) {
            int idx = tid + i * 256;
            int row = idx >> 2, cq = idx & 3;
            uint32_t soff = row * (SROW * 2) + cq * 16;
            cpasync16(sbase + A_TILE_B + soff, gBh + (size_t)row * Dd + k0 + cq * 8);
            cpasync16(sbase + A_TILE_B + B_TILE_B + soff, gBl + (size_t)row * Dd + k0 + cq * 8);
        }
    };

    float acc[2][4][4];
    #pragma unroll
    for (int i = 0; i < 2; i++)
        #pragma unroll
        for (int j = 0; j < 4; j++)
            #pragma unroll
            for (int q = 0; q < 4; q++) acc[i][j][q] = 0.f;

    // prologue: stages 0..2
    #pragma unroll
    for (int s = 0; s < 3; s++) { load_stage(s, s * KT); cpcommit(); }

    int g = lane >> 3, rIn = lane & 7;
    int aRowOff = wr * 32 + rIn + (g & 1) * 8;
    int aColOff = (g >> 1) * 8;
    int bRowOff = wc * 32 + rIn + (g >> 1) * 8;
    int bColOff = (g & 1) * 8;

    const int NKT = Dd / KT;   // 16
    #pragma unroll 1
    for (int kt = 0; kt < NKT; kt++) {
        cpwait<2>();
        __syncthreads();
        if (kt + 3 < NKT) load_stage((kt + 3) & 3, (kt + 3) * KT);
        cpcommit();

        uint32_t stage = sb + (kt & 3) * STAGE_B;
        #pragma unroll
        for (int ks = 0; ks < KT / 16; ks++) {
            int k16 = ks * 16;
            uint32_t a[2][4], bh[2][4], bl[2][4];
            #pragma unroll
            for (int mt = 0; mt < 2; mt++) {
                uint32_t ad = stage + 2 * ((aRowOff + mt * 16) * SROW + k16 + aColOff);
                ldsm4(ad, a[mt]);
            }
            #pragma unroll
            for (int np = 0; np < 2; np++) {
                uint32_t bd = stage + A_TILE_B + 2 * ((bRowOff + np * 16) * SROW + k16 + bColOff);
                ldsm4(bd, bh[np]);
                uint32_t bd2 = stage + A_TILE_B + B_TILE_B + 2 * ((bRowOff + np * 16) * SROW + k16 + bColOff);
                ldsm4(bd2, bl[np]);
            }
            #pragma unroll
            for (int mt = 0; mt < 2; mt++) {
                #pragma unroll
                for (int np = 0; np < 2; np++) {
                    #pragma unroll
                    for (int h = 0; h < 2; h++) {
                        int nt = np * 2 + h;
                        mma16816(acc[mt][nt], a[mt], bh[np][2 * h], bh[np][2 * h + 1]);
                        mma16816(acc[mt][nt], a[mt], bl[np][2 * h], bl[np][2 * h + 1]);
                    }
                }
            }
        }
    }

    // epilogue: per-row bias from ffb (rows are b*Mm + m; Mm == 512)
    int erow = lane >> 2, ecol2 = (lane & 3) * 2;
    #pragma unroll
    for (int mt = 0; mt < 2; mt++) {
        #pragma unroll
        for (int nt = 0; nt < 4; nt++) {
            int col = n0 + wc * 32 + nt * 8 + ecol2;
            int r0 = m0 + wr * 32 + mt * 16 + erow;
            int mm0 = r0 & (Mm - 1);
            float2 fb0 = *(const float2*)(g_ffb + mm0 * Dd + col);
            float2 fb1 = *(const float2*)(g_ffb + ((r0 + 8) & (Mm - 1)) * Dd + col);
            float2 v0 = make_float2(acc[mt][nt][0] + fb0.x, acc[mt][nt][1] + fb0.y);
            float2 v1 = make_float2(acc[mt][nt][2] + fb1.x, acc[mt][nt][3] + fb1.y);
            *(float2*)(out + (size_t)r0 * Dd + col) = v0;
            *(float2*)(out + (size_t)(r0 + 8) * Dd + col) = v1;
        }
    }
}

extern "C" void kernel_launch(void* const* d_in, const int* in_sizes, int n_in,
                              void* d_out, int out_size) {
    const float* frame  = (const float*)d_in[0];
    const void*  bounds = d_in[1];
    const float* Wm     = (const float*)d_in[2];
    const float* bias   = (const float*)d_in[3];
    float* out = (float*)d_out;

    cudaFuncSetAttribute(kGemmMMA, cudaFuncAttributeMaxDynamicSharedMemorySize, SM_BYTES);

    kFused<<<NBLK_TOTAL, 128>>>(frame, bounds, Wm, bias);
    kScan<<<dim3(128, Bb), 128>>>();
    kGather<<<dim3(Mm, Bb), 128>>>(frame);
    kGemmMMA<<<dim3(Dd / 128, (Bb * Mm) / 64), 256, SM_BYTES>>>(out);
}